// round 12
// baseline (speedup 1.0000x reference)
#include <cuda_runtime.h>
#include <cuda_bf16.h>
#include <math.h>
#include <cstdint>

// Problem constants
#define Bq   2
#define Nq   2048
#define Cq   1024
#define Hq   16
#define Dq   64
#define ROWS (Bq*Nq)          // 4096
#define QKVC (3*Cq)           // 3072

// Scratch (no cudaMalloc allowed)
__device__ float g_qkv[(size_t)ROWS * QKVC];      // [4096, 3072]
__device__ float g_attn[(size_t)ROWS * Cq];       // [4096, 1024]

// ---------------------------------------------------------------------------
// helpers
// ---------------------------------------------------------------------------
__device__ __forceinline__ uint32_t tf32_rna(float x) {
    uint32_t u;
    asm("cvt.rna.tf32.f32 %0, %1;" : "=r"(u) : "f"(x));
    return u;
}
__device__ __forceinline__ void mma_tf32(float* d, const uint32_t* a,
                                         const uint32_t* b) {
    asm volatile(
        "mma.sync.aligned.m16n8k8.row.col.f32.tf32.tf32.f32 "
        "{%0,%1,%2,%3}, {%4,%5,%6,%7}, {%8,%9}, {%0,%1,%2,%3};"
        : "+f"(d[0]), "+f"(d[1]), "+f"(d[2]), "+f"(d[3])
        : "r"(a[0]), "r"(a[1]), "r"(a[2]), "r"(a[3]),
          "r"(b[0]), "r"(b[1]));
}

// ===========================================================================
// TF32 mma.sync GEMM: C[M,N] = A[M,K] @ B[K,N] + bias[N]
// CTA tile 128x128, BK=32, 256 threads (8 warps, 4x2), warp tile 32x64.
// Fragment layout (m16n8k8):
//   A: a0=(r, c) a1=(r+8, c) a2=(r, c+4) a3=(r+8, c+4)   [r=lane/4, c=lane%4]
//   B: b0=(k=c, n=r) b1=(k=c+4, n=r)
//   D: c0=(r, 2c) c1=(r, 2c+1) c2=(r+8, 2c) c3=(r+8, 2c+1)
// Smem strides 36 / 136 give conflict-free fragment loads.
// ===========================================================================
#define AS_STRIDE 36
#define BS_STRIDE 136

__global__ __launch_bounds__(256, 2)
void gemm_mma_tf32(const float* __restrict__ A, const float* __restrict__ B,
                   const float* __restrict__ bias, float* __restrict__ C,
                   int M, int N, int K)
{
    __shared__ alignas(16) uint32_t As[128 * AS_STRIDE];  // [m][k], tf32
    __shared__ alignas(16) uint32_t Bs[32 * BS_STRIDE];   // [k][n], tf32

    const int tid  = threadIdx.x;
    const int lane = tid & 31;
    const int wid  = tid >> 5;
    const int wm   = wid & 3;          // warp row 0..3  (32 rows each)
    const int wn   = wid >> 2;         // warp col 0..1  (64 cols each)
    const int brow = blockIdx.y * 128;
    const int bcol = blockIdx.x * 128;
    const int r = lane >> 2;           // 0..7
    const int c = lane & 3;            // 0..3

    float acc[2][8][4];
#pragma unroll
    for (int mt = 0; mt < 2; mt++)
#pragma unroll
        for (int nt = 0; nt < 8; nt++)
#pragma unroll
            for (int j = 0; j < 4; j++) acc[mt][nt][j] = 0.f;

    for (int k0 = 0; k0 < K; k0 += 32) {
        // Stage A (128x32) -> As[m][k]
#pragma unroll
        for (int i = 0; i < 4; i++) {
            int g   = tid + i * 256;         // 0..1023
            int row = g >> 3;                // 0..127
            int col = (g & 7) * 4;           // 0..28
            float4 a4 = *reinterpret_cast<const float4*>(
                &A[(size_t)(brow + row) * K + k0 + col]);
            uint4 u = { tf32_rna(a4.x), tf32_rna(a4.y),
                        tf32_rna(a4.z), tf32_rna(a4.w) };
            *reinterpret_cast<uint4*>(&As[row * AS_STRIDE + col]) = u;
        }
        // Stage B (32x128) -> Bs[k][n]
#pragma unroll
        for (int i = 0; i < 4; i++) {
            int g   = tid + i * 256;
            int row = g >> 5;                // 0..31
            int col = (g & 31) * 4;          // 0..124
            float4 b4 = *reinterpret_cast<const float4*>(
                &B[(size_t)(k0 + row) * N + bcol + col]);
            uint4 u = { tf32_rna(b4.x), tf32_rna(b4.y),
                        tf32_rna(b4.z), tf32_rna(b4.w) };
            *reinterpret_cast<uint4*>(&Bs[row * BS_STRIDE + col]) = u;
        }
        __syncthreads();

#pragma unroll
        for (int ks = 0; ks < 32; ks += 8) {
            uint32_t af[2][4];
            uint32_t bf[8][2];
#pragma unroll
            for (int mt = 0; mt < 2; mt++) {
                int rb = (wm * 32 + mt * 16 + r) * AS_STRIDE + ks + c;
                af[mt][0] = As[rb];
                af[mt][1] = As[rb + 8 * AS_STRIDE];
                af[mt][2] = As[rb + 4];
                af[mt][3] = As[rb + 8 * AS_STRIDE + 4];
            }
#pragma unroll
            for (int nt = 0; nt < 8; nt++) {
                int nb = wn * 64 + nt * 8 + r;
                bf[nt][0] = Bs[(ks + c) * BS_STRIDE + nb];
                bf[nt][1] = Bs[(ks + c + 4) * BS_STRIDE + nb];
            }
#pragma unroll
            for (int mt = 0; mt < 2; mt++)
#pragma unroll
                for (int nt = 0; nt < 8; nt++)
                    mma_tf32(acc[mt][nt], af[mt], bf[nt]);
        }
        __syncthreads();
    }

    // Epilogue: bias + store (float2 per fragment row)
#pragma unroll
    for (int mt = 0; mt < 2; mt++) {
#pragma unroll
        for (int nt = 0; nt < 8; nt++) {
            int row = brow + wm * 32 + mt * 16 + r;
            int col = bcol + wn * 64 + nt * 8 + c * 2;
            float bx = bias[col], by = bias[col + 1];
            float2 v0 = { acc[mt][nt][0] + bx, acc[mt][nt][1] + by };
            float2 v1 = { acc[mt][nt][2] + bx, acc[mt][nt][3] + by };
            *reinterpret_cast<float2*>(&C[(size_t)row * N + col])       = v0;
            *reinterpret_cast<float2*>(&C[(size_t)(row + 8) * N + col]) = v1;
        }
    }
}

// ---------------------------------------------------------------------------
// Per-head RMSNorm on q and k, in place on the QKV buffer.
// ---------------------------------------------------------------------------
__global__ __launch_bounds__(256)
void qk_rmsnorm(float* __restrict__ Y,
                const float* __restrict__ qw, const float* __restrict__ kw)
{
    int gwarp = (blockIdx.x * blockDim.x + threadIdx.x) >> 5;
    int lane  = threadIdx.x & 31;
    const int total = ROWS * Hq * 2;
    if (gwarp >= total) return;

    int which = gwarp & 1;
    int h     = (gwarp >> 1) & (Hq - 1);
    int row   = gwarp >> 5;

    float* p = Y + (size_t)row * QKVC + which * Cq + h * Dq;
    const float* w = which ? kw : qw;

    float x0 = p[lane];
    float x1 = p[lane + 32];
    float ss = x0 * x0 + x1 * x1;
#pragma unroll
    for (int o = 16; o > 0; o >>= 1)
        ss += __shfl_xor_sync(0xffffffffu, ss, o);
    float r = rsqrtf(ss * (1.0f / Dq) + 1e-6f);
    p[lane]      = x0 * r * w[lane];
    p[lane + 32] = x1 * r * w[lane + 32];
}

// ---------------------------------------------------------------------------
// Flash-style attention, fp32 SIMT (unchanged from R1-passing version).
// ---------------------------------------------------------------------------
#define ATS 65
#define ATTN_SMEM_FLOATS (4 * 64 * ATS + 3 * 64 + 64 * 16)
#define ATTN_SMEM_BYTES  (ATTN_SMEM_FLOATS * 4)

__global__ __launch_bounds__(256)
void attn_kernel(const float* __restrict__ Y, float* __restrict__ AO)
{
    extern __shared__ float sm[];
    float* Qs   = sm;
    float* Kt   = Qs  + 64 * ATS;
    float* Vs   = Kt  + 64 * ATS;
    float* Ps   = Vs  + 64 * ATS;
    float* mrow = Ps  + 64 * ATS;
    float* lrow = mrow + 64;
    float* frow = lrow + 64;
    float* red  = frow + 64;

    const int tid = threadIdx.x;
    const int ty  = tid >> 4;
    const int tx  = tid & 15;
    const int b   = blockIdx.z;
    const int h   = blockIdx.y;
    const int q0  = blockIdx.x * 64;

    const float* Yb = Y + (size_t)b * Nq * QKVC;
    const int qcol = h * Dq;
    const int kcol = Cq + h * Dq;
    const int vcol = 2 * Cq + h * Dq;

#pragma unroll
    for (int i = 0; i < 4; i++) {
        int g = tid + i * 256;
        int r = g >> 4;
        int c = (g & 15) * 4;
        float4 v = *reinterpret_cast<const float4*>(
            &Yb[(size_t)(q0 + r) * QKVC + qcol + c]);
        float* dst = &Qs[r * ATS + c];
        dst[0] = v.x; dst[1] = v.y; dst[2] = v.z; dst[3] = v.w;
    }
    if (tid < 64) { mrow[tid] = -1e30f; lrow[tid] = 0.f; }

    float o[4][4];
#pragma unroll
    for (int i = 0; i < 4; i++)
#pragma unroll
        for (int j = 0; j < 4; j++) o[i][j] = 0.f;

    __syncthreads();

    const float scale = 0.125f;

    for (int j0 = 0; j0 < Nq; j0 += 64) {
#pragma unroll
        for (int i = 0; i < 4; i++) {
            int g = tid + i * 256;
            int c = g >> 4;
            int d = (g & 15) * 4;
            const size_t base = (size_t)(j0 + c) * QKVC;
            float4 kk = *reinterpret_cast<const float4*>(&Yb[base + kcol + d]);
            Kt[(d + 0) * ATS + c] = kk.x;
            Kt[(d + 1) * ATS + c] = kk.y;
            Kt[(d + 2) * ATS + c] = kk.z;
            Kt[(d + 3) * ATS + c] = kk.w;
            float4 vv = *reinterpret_cast<const float4*>(&Yb[base + vcol + d]);
            float* vd = &Vs[c * ATS + d];
            vd[0] = vv.x; vd[1] = vv.y; vd[2] = vv.z; vd[3] = vv.w;
        }
        __syncthreads();

        float s[4][4];
#pragma unroll
        for (int i = 0; i < 4; i++)
#pragma unroll
            for (int j = 0; j < 4; j++) s[i][j] = 0.f;

        for (int d = 0; d < 64; d++) {
            float a0 = Qs[(ty * 4 + 0) * ATS + d];
            float a1 = Qs[(ty * 4 + 1) * ATS + d];
            float a2 = Qs[(ty * 4 + 2) * ATS + d];
            float a3 = Qs[(ty * 4 + 3) * ATS + d];
            float b0 = Kt[d * ATS + tx * 4 + 0];
            float b1 = Kt[d * ATS + tx * 4 + 1];
            float b2 = Kt[d * ATS + tx * 4 + 2];
            float b3 = Kt[d * ATS + tx * 4 + 3];
            s[0][0] = fmaf(a0, b0, s[0][0]); s[0][1] = fmaf(a0, b1, s[0][1]);
            s[0][2] = fmaf(a0, b2, s[0][2]); s[0][3] = fmaf(a0, b3, s[0][3]);
            s[1][0] = fmaf(a1, b0, s[1][0]); s[1][1] = fmaf(a1, b1, s[1][1]);
            s[1][2] = fmaf(a1, b2, s[1][2]); s[1][3] = fmaf(a1, b3, s[1][3]);
            s[2][0] = fmaf(a2, b0, s[2][0]); s[2][1] = fmaf(a2, b1, s[2][1]);
            s[2][2] = fmaf(a2, b2, s[2][2]); s[2][3] = fmaf(a2, b3, s[2][3]);
            s[3][0] = fmaf(a3, b0, s[3][0]); s[3][1] = fmaf(a3, b1, s[3][1]);
            s[3][2] = fmaf(a3, b2, s[3][2]); s[3][3] = fmaf(a3, b3, s[3][3]);
        }

#pragma unroll
        for (int i = 0; i < 4; i++) {
            float pm = -1e30f;
#pragma unroll
            for (int j = 0; j < 4; j++) {
                s[i][j] *= scale;
                pm = fmaxf(pm, s[i][j]);
            }
            red[(ty * 4 + i) * 16 + tx] = pm;
        }
        __syncthreads();

        if (tid < 64) {
            float rm = red[tid * 16];
#pragma unroll
            for (int t = 1; t < 16; t++) rm = fmaxf(rm, red[tid * 16 + t]);
            float mo = mrow[tid];
            float mn = fmaxf(mo, rm);
            frow[tid] = __expf(mo - mn);
            mrow[tid] = mn;
        }
        __syncthreads();

#pragma unroll
        for (int i = 0; i < 4; i++) {
            float mn = mrow[ty * 4 + i];
            float ps = 0.f;
#pragma unroll
            for (int j = 0; j < 4; j++) {
                float p = __expf(s[i][j] - mn);
                Ps[(ty * 4 + i) * ATS + tx * 4 + j] = p;
                ps += p;
            }
            red[(ty * 4 + i) * 16 + tx] = ps;
        }
        __syncthreads();

        if (tid < 64) {
            float rs = 0.f;
#pragma unroll
            for (int t = 0; t < 16; t++) rs += red[tid * 16 + t];
            lrow[tid] = lrow[tid] * frow[tid] + rs;
        }

        float f0 = frow[ty * 4 + 0], f1 = frow[ty * 4 + 1];
        float f2 = frow[ty * 4 + 2], f3 = frow[ty * 4 + 3];
#pragma unroll
        for (int j = 0; j < 4; j++) {
            o[0][j] *= f0; o[1][j] *= f1; o[2][j] *= f2; o[3][j] *= f3;
        }
        for (int c = 0; c < 64; c++) {
            float p0 = Ps[(ty * 4 + 0) * ATS + c];
            float p1 = Ps[(ty * 4 + 1) * ATS + c];
            float p2 = Ps[(ty * 4 + 2) * ATS + c];
            float p3 = Ps[(ty * 4 + 3) * ATS + c];
            float v0 = Vs[c * ATS + tx * 4 + 0];
            float v1 = Vs[c * ATS + tx * 4 + 1];
            float v2 = Vs[c * ATS + tx * 4 + 2];
            float v3 = Vs[c * ATS + tx * 4 + 3];
            o[0][0] = fmaf(p0, v0, o[0][0]); o[0][1] = fmaf(p0, v1, o[0][1]);
            o[0][2] = fmaf(p0, v2, o[0][2]); o[0][3] = fmaf(p0, v3, o[0][3]);
            o[1][0] = fmaf(p1, v0, o[1][0]); o[1][1] = fmaf(p1, v1, o[1][1]);
            o[1][2] = fmaf(p1, v2, o[1][2]); o[1][3] = fmaf(p1, v3, o[1][3]);
            o[2][0] = fmaf(p2, v0, o[2][0]); o[2][1] = fmaf(p2, v1, o[2][1]);
            o[2][2] = fmaf(p2, v2, o[2][2]); o[2][3] = fmaf(p2, v3, o[2][3]);
            o[3][0] = fmaf(p3, v0, o[3][0]); o[3][1] = fmaf(p3, v1, o[3][1]);
            o[3][2] = fmaf(p3, v2, o[3][2]); o[3][3] = fmaf(p3, v3, o[3][3]);
        }
        __syncthreads();
    }

#pragma unroll
    for (int i = 0; i < 4; i++) {
        float inv = 1.0f / lrow[ty * 4 + i];
        size_t base = (size_t)(b * Nq + q0 + ty * 4 + i) * Cq + h * Dq + tx * 4;
#pragma unroll
        for (int j = 0; j < 4; j++)
            AO[base + j] = o[i][j] * inv;
    }
}

// ---------------------------------------------------------------------------
// Host launcher
// ---------------------------------------------------------------------------
extern "C" void kernel_launch(void* const* d_in, const int* in_sizes, int n_in,
                              void* d_out, int out_size)
{
    const float* x      = (const float*)d_in[0];
    const float* w_qkv  = (const float*)d_in[1];
    const float* b_qkv  = (const float*)d_in[2];
    const float* q_w    = (const float*)d_in[3];
    const float* k_w    = (const float*)d_in[4];
    const float* w_proj = (const float*)d_in[5];
    const float* b_proj = (const float*)d_in[6];
    float* out          = (float*)d_out;

    void *qkv_p, *att_p;
    cudaGetSymbolAddress(&qkv_p, g_qkv);
    cudaGetSymbolAddress(&att_p, g_attn);
    float* qkv = (float*)qkv_p;
    float* att = (float*)att_p;

    // 1) QKV projection (mma.sync tf32)
    {
        dim3 grid(QKVC / 128, ROWS / 128);
        gemm_mma_tf32<<<grid, 256>>>(x, w_qkv, b_qkv, qkv, ROWS, QKVC, Cq);
    }

    // 2) per-head RMSNorm on q,k
    {
        int warps = ROWS * Hq * 2;
        int blocks = warps / 8;
        qk_rmsnorm<<<blocks, 256>>>(qkv, q_w, k_w);
    }

    // 3) attention (fp32 SIMT flash)
    {
        cudaFuncSetAttribute(attn_kernel,
                             cudaFuncAttributeMaxDynamicSharedMemorySize,
                             ATTN_SMEM_BYTES);
        dim3 grid(Nq / 64, Hq, Bq);
        attn_kernel<<<grid, 256, ATTN_SMEM_BYTES>>>(qkv, att);
    }

    // 4) output projection (mma.sync tf32)
    {
        dim3 grid(Cq / 128, ROWS / 128);
        gemm_mma_tf32<<<grid, 256>>>(att, w_proj, b_proj, out, ROWS, Cq, Cq);
    }
}

// round 13
// speedup vs baseline: 1.0019x; 1.0019x over previous
#include <cuda_runtime.h>
#include <cuda_bf16.h>
#include <math.h>
#include <cstdint>

// Problem constants
#define Bq   2
#define Nq   2048
#define Cq   1024
#define Hq   16
#define Dq   64
#define ROWS (Bq*Nq)          // 4096
#define QKVC (3*Cq)           // 3072

// Scratch (no cudaMalloc allowed)
__device__ float g_qkv[(size_t)ROWS * QKVC];      // [4096, 3072]
__device__ float g_attn[(size_t)ROWS * Cq];       // [4096, 1024]

// ---------------------------------------------------------------------------
// helpers
// ---------------------------------------------------------------------------
__device__ __forceinline__ uint32_t tf32_rna(float x) {
    uint32_t u;
    asm("cvt.rna.tf32.f32 %0, %1;" : "=r"(u) : "f"(x));
    return u;
}
__device__ __forceinline__ void mma_tf32(float* d, const uint32_t* a,
                                         const uint32_t* b) {
    asm volatile(
        "mma.sync.aligned.m16n8k8.row.col.f32.tf32.tf32.f32 "
        "{%0,%1,%2,%3}, {%4,%5,%6,%7}, {%8,%9}, {%0,%1,%2,%3};"
        : "+f"(d[0]), "+f"(d[1]), "+f"(d[2]), "+f"(d[3])
        : "r"(a[0]), "r"(a[1]), "r"(a[2]), "r"(a[3]),
          "r"(b[0]), "r"(b[1]));
}

// ===========================================================================
// TF32 mma.sync GEMM: C[M,N] = A[M,K] @ B[K,N] + bias[N]
// CTA tile 128x128, BK=32, 256 threads (8 warps, 4x2), warp tile 32x64.
// Fragment layout (m16n8k8):
//   A: a0=(r, c) a1=(r+8, c) a2=(r, c+4) a3=(r+8, c+4)   [r=lane/4, c=lane%4]
//   B: b0=(k=c, n=r) b1=(k=c+4, n=r)
//   D: c0=(r, 2c) c1=(r, 2c+1) c2=(r+8, 2c) c3=(r+8, 2c+1)
// Smem strides 36 / 136 give conflict-free fragment loads.
// ===========================================================================
#define AS_STRIDE 36
#define BS_STRIDE 136

__global__ __launch_bounds__(256, 2)
void gemm_mma_tf32(const float* __restrict__ A, const float* __restrict__ B,
                   const float* __restrict__ bias, float* __restrict__ C,
                   int M, int N, int K)
{
    __shared__ alignas(16) uint32_t As[128 * AS_STRIDE];  // [m][k], tf32
    __shared__ alignas(16) uint32_t Bs[32 * BS_STRIDE];   // [k][n], tf32

    const int tid  = threadIdx.x;
    const int lane = tid & 31;
    const int wid  = tid >> 5;
    const int wm   = wid & 3;          // warp row 0..3  (32 rows each)
    const int wn   = wid >> 2;         // warp col 0..1  (64 cols each)
    const int brow = blockIdx.y * 128;
    const int bcol = blockIdx.x * 128;
    const int r = lane >> 2;           // 0..7
    const int c = lane & 3;            // 0..3

    float acc[2][8][4];
#pragma unroll
    for (int mt = 0; mt < 2; mt++)
#pragma unroll
        for (int nt = 0; nt < 8; nt++)
#pragma unroll
            for (int j = 0; j < 4; j++) acc[mt][nt][j] = 0.f;

    for (int k0 = 0; k0 < K; k0 += 32) {
        // Stage A (128x32) -> As[m][k]
#pragma unroll
        for (int i = 0; i < 4; i++) {
            int g   = tid + i * 256;         // 0..1023
            int row = g >> 3;                // 0..127
            int col = (g & 7) * 4;           // 0..28
            float4 a4 = *reinterpret_cast<const float4*>(
                &A[(size_t)(brow + row) * K + k0 + col]);
            uint4 u = { tf32_rna(a4.x), tf32_rna(a4.y),
                        tf32_rna(a4.z), tf32_rna(a4.w) };
            *reinterpret_cast<uint4*>(&As[row * AS_STRIDE + col]) = u;
        }
        // Stage B (32x128) -> Bs[k][n]
#pragma unroll
        for (int i = 0; i < 4; i++) {
            int g   = tid + i * 256;
            int row = g >> 5;                // 0..31
            int col = (g & 31) * 4;          // 0..124
            float4 b4 = *reinterpret_cast<const float4*>(
                &B[(size_t)(k0 + row) * N + bcol + col]);
            uint4 u = { tf32_rna(b4.x), tf32_rna(b4.y),
                        tf32_rna(b4.z), tf32_rna(b4.w) };
            *reinterpret_cast<uint4*>(&Bs[row * BS_STRIDE + col]) = u;
        }
        __syncthreads();

#pragma unroll
        for (int ks = 0; ks < 32; ks += 8) {
            uint32_t af[2][4];
            uint32_t bf[8][2];
#pragma unroll
            for (int mt = 0; mt < 2; mt++) {
                int rb = (wm * 32 + mt * 16 + r) * AS_STRIDE + ks + c;
                af[mt][0] = As[rb];
                af[mt][1] = As[rb + 8 * AS_STRIDE];
                af[mt][2] = As[rb + 4];
                af[mt][3] = As[rb + 8 * AS_STRIDE + 4];
            }
#pragma unroll
            for (int nt = 0; nt < 8; nt++) {
                int nb = wn * 64 + nt * 8 + r;
                bf[nt][0] = Bs[(ks + c) * BS_STRIDE + nb];
                bf[nt][1] = Bs[(ks + c + 4) * BS_STRIDE + nb];
            }
#pragma unroll
            for (int mt = 0; mt < 2; mt++)
#pragma unroll
                for (int nt = 0; nt < 8; nt++)
                    mma_tf32(acc[mt][nt], af[mt], bf[nt]);
        }
        __syncthreads();
    }

    // Epilogue: bias + store (float2 per fragment row)
#pragma unroll
    for (int mt = 0; mt < 2; mt++) {
#pragma unroll
        for (int nt = 0; nt < 8; nt++) {
            int row = brow + wm * 32 + mt * 16 + r;
            int col = bcol + wn * 64 + nt * 8 + c * 2;
            float bx = bias[col], by = bias[col + 1];
            float2 v0 = { acc[mt][nt][0] + bx, acc[mt][nt][1] + by };
            float2 v1 = { acc[mt][nt][2] + bx, acc[mt][nt][3] + by };
            *reinterpret_cast<float2*>(&C[(size_t)row * N + col])       = v0;
            *reinterpret_cast<float2*>(&C[(size_t)(row + 8) * N + col]) = v1;
        }
    }
}

// ---------------------------------------------------------------------------
// Per-head RMSNorm on q and k, in place on the QKV buffer.
// ---------------------------------------------------------------------------
__global__ __launch_bounds__(256)
void qk_rmsnorm(float* __restrict__ Y,
                const float* __restrict__ qw, const float* __restrict__ kw)
{
    int gwarp = (blockIdx.x * blockDim.x + threadIdx.x) >> 5;
    int lane  = threadIdx.x & 31;
    const int total = ROWS * Hq * 2;
    if (gwarp >= total) return;

    int which = gwarp & 1;
    int h     = (gwarp >> 1) & (Hq - 1);
    int row   = gwarp >> 5;

    float* p = Y + (size_t)row * QKVC + which * Cq + h * Dq;
    const float* w = which ? kw : qw;

    float x0 = p[lane];
    float x1 = p[lane + 32];
    float ss = x0 * x0 + x1 * x1;
#pragma unroll
    for (int o = 16; o > 0; o >>= 1)
        ss += __shfl_xor_sync(0xffffffffu, ss, o);
    float r = rsqrtf(ss * (1.0f / Dq) + 1e-6f);
    p[lane]      = x0 * r * w[lane];
    p[lane + 32] = x1 * r * w[lane + 32];
}

// ---------------------------------------------------------------------------
// Flash-style attention, fp32 SIMT (unchanged from R1-passing version).
// ---------------------------------------------------------------------------
#define ATS 65
#define ATTN_SMEM_FLOATS (4 * 64 * ATS + 3 * 64 + 64 * 16)
#define ATTN_SMEM_BYTES  (ATTN_SMEM_FLOATS * 4)

__global__ __launch_bounds__(256)
void attn_kernel(const float* __restrict__ Y, float* __restrict__ AO)
{
    extern __shared__ float sm[];
    float* Qs   = sm;
    float* Kt   = Qs  + 64 * ATS;
    float* Vs   = Kt  + 64 * ATS;
    float* Ps   = Vs  + 64 * ATS;
    float* mrow = Ps  + 64 * ATS;
    float* lrow = mrow + 64;
    float* frow = lrow + 64;
    float* red  = frow + 64;

    const int tid = threadIdx.x;
    const int ty  = tid >> 4;
    const int tx  = tid & 15;
    const int b   = blockIdx.z;
    const int h   = blockIdx.y;
    const int q0  = blockIdx.x * 64;

    const float* Yb = Y + (size_t)b * Nq * QKVC;
    const int qcol = h * Dq;
    const int kcol = Cq + h * Dq;
    const int vcol = 2 * Cq + h * Dq;

#pragma unroll
    for (int i = 0; i < 4; i++) {
        int g = tid + i * 256;
        int r = g >> 4;
        int c = (g & 15) * 4;
        float4 v = *reinterpret_cast<const float4*>(
            &Yb[(size_t)(q0 + r) * QKVC + qcol + c]);
        float* dst = &Qs[r * ATS + c];
        dst[0] = v.x; dst[1] = v.y; dst[2] = v.z; dst[3] = v.w;
    }
    if (tid < 64) { mrow[tid] = -1e30f; lrow[tid] = 0.f; }

    float o[4][4];
#pragma unroll
    for (int i = 0; i < 4; i++)
#pragma unroll
        for (int j = 0; j < 4; j++) o[i][j] = 0.f;

    __syncthreads();

    const float scale = 0.125f;

    for (int j0 = 0; j0 < Nq; j0 += 64) {
#pragma unroll
        for (int i = 0; i < 4; i++) {
            int g = tid + i * 256;
            int c = g >> 4;
            int d = (g & 15) * 4;
            const size_t base = (size_t)(j0 + c) * QKVC;
            float4 kk = *reinterpret_cast<const float4*>(&Yb[base + kcol + d]);
            Kt[(d + 0) * ATS + c] = kk.x;
            Kt[(d + 1) * ATS + c] = kk.y;
            Kt[(d + 2) * ATS + c] = kk.z;
            Kt[(d + 3) * ATS + c] = kk.w;
            float4 vv = *reinterpret_cast<const float4*>(&Yb[base + vcol + d]);
            float* vd = &Vs[c * ATS + d];
            vd[0] = vv.x; vd[1] = vv.y; vd[2] = vv.z; vd[3] = vv.w;
        }
        __syncthreads();

        float s[4][4];
#pragma unroll
        for (int i = 0; i < 4; i++)
#pragma unroll
            for (int j = 0; j < 4; j++) s[i][j] = 0.f;

        for (int d = 0; d < 64; d++) {
            float a0 = Qs[(ty * 4 + 0) * ATS + d];
            float a1 = Qs[(ty * 4 + 1) * ATS + d];
            float a2 = Qs[(ty * 4 + 2) * ATS + d];
            float a3 = Qs[(ty * 4 + 3) * ATS + d];
            float b0 = Kt[d * ATS + tx * 4 + 0];
            float b1 = Kt[d * ATS + tx * 4 + 1];
            float b2 = Kt[d * ATS + tx * 4 + 2];
            float b3 = Kt[d * ATS + tx * 4 + 3];
            s[0][0] = fmaf(a0, b0, s[0][0]); s[0][1] = fmaf(a0, b1, s[0][1]);
            s[0][2] = fmaf(a0, b2, s[0][2]); s[0][3] = fmaf(a0, b3, s[0][3]);
            s[1][0] = fmaf(a1, b0, s[1][0]); s[1][1] = fmaf(a1, b1, s[1][1]);
            s[1][2] = fmaf(a1, b2, s[1][2]); s[1][3] = fmaf(a1, b3, s[1][3]);
            s[2][0] = fmaf(a2, b0, s[2][0]); s[2][1] = fmaf(a2, b1, s[2][1]);
            s[2][2] = fmaf(a2, b2, s[2][2]); s[2][3] = fmaf(a2, b3, s[2][3]);
            s[3][0] = fmaf(a3, b0, s[3][0]); s[3][1] = fmaf(a3, b1, s[3][1]);
            s[3][2] = fmaf(a3, b2, s[3][2]); s[3][3] = fmaf(a3, b3, s[3][3]);
        }

#pragma unroll
        for (int i = 0; i < 4; i++) {
            float pm = -1e30f;
#pragma unroll
            for (int j = 0; j < 4; j++) {
                s[i][j] *= scale;
                pm = fmaxf(pm, s[i][j]);
            }
            red[(ty * 4 + i) * 16 + tx] = pm;
        }
        __syncthreads();

        if (tid < 64) {
            float rm = red[tid * 16];
#pragma unroll
            for (int t = 1; t < 16; t++) rm = fmaxf(rm, red[tid * 16 + t]);
            float mo = mrow[tid];
            float mn = fmaxf(mo, rm);
            frow[tid] = __expf(mo - mn);
            mrow[tid] = mn;
        }
        __syncthreads();

#pragma unroll
        for (int i = 0; i < 4; i++) {
            float mn = mrow[ty * 4 + i];
            float ps = 0.f;
#pragma unroll
            for (int j = 0; j < 4; j++) {
                float p = __expf(s[i][j] - mn);
                Ps[(ty * 4 + i) * ATS + tx * 4 + j] = p;
                ps += p;
            }
            red[(ty * 4 + i) * 16 + tx] = ps;
        }
        __syncthreads();

        if (tid < 64) {
            float rs = 0.f;
#pragma unroll
            for (int t = 0; t < 16; t++) rs += red[tid * 16 + t];
            lrow[tid] = lrow[tid] * frow[tid] + rs;
        }

        float f0 = frow[ty * 4 + 0], f1 = frow[ty * 4 + 1];
        float f2 = frow[ty * 4 + 2], f3 = frow[ty * 4 + 3];
#pragma unroll
        for (int j = 0; j < 4; j++) {
            o[0][j] *= f0; o[1][j] *= f1; o[2][j] *= f2; o[3][j] *= f3;
        }
        for (int c = 0; c < 64; c++) {
            float p0 = Ps[(ty * 4 + 0) * ATS + c];
            float p1 = Ps[(ty * 4 + 1) * ATS + c];
            float p2 = Ps[(ty * 4 + 2) * ATS + c];
            float p3 = Ps[(ty * 4 + 3) * ATS + c];
            float v0 = Vs[c * ATS + tx * 4 + 0];
            float v1 = Vs[c * ATS + tx * 4 + 1];
            float v2 = Vs[c * ATS + tx * 4 + 2];
            float v3 = Vs[c * ATS + tx * 4 + 3];
            o[0][0] = fmaf(p0, v0, o[0][0]); o[0][1] = fmaf(p0, v1, o[0][1]);
            o[0][2] = fmaf(p0, v2, o[0][2]); o[0][3] = fmaf(p0, v3, o[0][3]);
            o[1][0] = fmaf(p1, v0, o[1][0]); o[1][1] = fmaf(p1, v1, o[1][1]);
            o[1][2] = fmaf(p1, v2, o[1][2]); o[1][3] = fmaf(p1, v3, o[1][3]);
            o[2][0] = fmaf(p2, v0, o[2][0]); o[2][1] = fmaf(p2, v1, o[2][1]);
            o[2][2] = fmaf(p2, v2, o[2][2]); o[2][3] = fmaf(p2, v3, o[2][3]);
            o[3][0] = fmaf(p3, v0, o[3][0]); o[3][1] = fmaf(p3, v1, o[3][1]);
            o[3][2] = fmaf(p3, v2, o[3][2]); o[3][3] = fmaf(p3, v3, o[3][3]);
        }
        __syncthreads();
    }

#pragma unroll
    for (int i = 0; i < 4; i++) {
        float inv = 1.0f / lrow[ty * 4 + i];
        size_t base = (size_t)(b * Nq + q0 + ty * 4 + i) * Cq + h * Dq + tx * 4;
#pragma unroll
        for (int j = 0; j < 4; j++)
            AO[base + j] = o[i][j] * inv;
    }
}

// ---------------------------------------------------------------------------
// Host launcher
// ---------------------------------------------------------------------------
extern "C" void kernel_launch(void* const* d_in, const int* in_sizes, int n_in,
                              void* d_out, int out_size)
{
    const float* x      = (const float*)d_in[0];
    const float* w_qkv  = (const float*)d_in[1];
    const float* b_qkv  = (const float*)d_in[2];
    const float* q_w    = (const float*)d_in[3];
    const float* k_w    = (const float*)d_in[4];
    const float* w_proj = (const float*)d_in[5];
    const float* b_proj = (const float*)d_in[6];
    float* out          = (float*)d_out;

    void *qkv_p, *att_p;
    cudaGetSymbolAddress(&qkv_p, g_qkv);
    cudaGetSymbolAddress(&att_p, g_attn);
    float* qkv = (float*)qkv_p;
    float* att = (float*)att_p;

    // 1) QKV projection (mma.sync tf32)
    {
        dim3 grid(QKVC / 128, ROWS / 128);
        gemm_mma_tf32<<<grid, 256>>>(x, w_qkv, b_qkv, qkv, ROWS, QKVC, Cq);
    }

    // 2) per-head RMSNorm on q,k
    {
        int warps = ROWS * Hq * 2;
        int blocks = warps / 8;
        qk_rmsnorm<<<blocks, 256>>>(qkv, q_w, k_w);
    }

    // 3) attention (fp32 SIMT flash)
    {
        cudaFuncSetAttribute(attn_kernel,
                             cudaFuncAttributeMaxDynamicSharedMemorySize,
                             ATTN_SMEM_BYTES);
        dim3 grid(Nq / 64, Hq, Bq);
        attn_kernel<<<grid, 256, ATTN_SMEM_BYTES>>>(qkv, att);
    }

    // 4) output projection (mma.sync tf32)
    {
        dim3 grid(Cq / 128, ROWS / 128);
        gemm_mma_tf32<<<grid, 256>>>(att, w_proj, b_proj, out, ROWS, Cq, Cq);
    }
}